// round 7
// baseline (speedup 1.0000x reference)
#include <cuda_runtime.h>
#include <cuda_bf16.h>

#define MAX_ROWS 8192
#define TILE_FLOATS 4000                 // 16000 B per tile; 8 exact tiles per 32000-float row
#define TILE_BYTES  (TILE_FLOATS * 4)
#define NSLOTS 3                         // SMEM ring slots
#define DEPTH  2                         // bulk copies in flight

__device__ double g_row_loss[MAX_ROWS];
__device__ unsigned int g_done = 0;      // self-resets -> graph-replay safe

__device__ __forceinline__ float ex2(float x) {
    float y;
    asm("ex2.approx.f32 %0, %1;" : "=f"(y) : "f"(x));
    return y;
}

__device__ __forceinline__ unsigned int smem_u32(const void* p) {
    return (unsigned int)__cvta_generic_to_shared(p);
}

__device__ __forceinline__ void mbar_init(unsigned int bar, unsigned int cnt) {
    asm volatile("mbarrier.init.shared.b64 [%0], %1;" :: "r"(bar), "r"(cnt) : "memory");
}
__device__ __forceinline__ void mbar_expect_tx(unsigned int bar, unsigned int bytes) {
    asm volatile("mbarrier.arrive.expect_tx.shared.b64 _, [%0], %1;"
                 :: "r"(bar), "r"(bytes) : "memory");
}
__device__ __forceinline__ void mbar_wait(unsigned int bar, unsigned int parity) {
    unsigned int done;
    asm volatile(
        "{\n\t.reg .pred p;\n\t"
        "mbarrier.try_wait.parity.acquire.cta.shared::cta.b64 p, [%1], %2;\n\t"
        "selp.b32 %0, 1, 0, p;\n\t}"
        : "=r"(done) : "r"(bar), "r"(parity) : "memory");
    if (!done) {
        asm volatile(
            "{\n\t.reg .pred P1;\n\t"
            "WL_%=:\n\t"
            "mbarrier.try_wait.parity.acquire.cta.shared::cta.b64 P1, [%0], %1, 0x989680;\n\t"
            "@P1 bra.uni WD_%=;\n\t"
            "bra.uni WL_%=;\n\t"
            "WD_%=:\n\t}"
            :: "r"(bar), "r"(parity) : "memory");
    }
}
__device__ __forceinline__ void bulk_g2s(unsigned int dst, const void* src,
                                         unsigned int bytes, unsigned int bar) {
    asm volatile(
        "cp.async.bulk.shared::cta.global.mbarrier::complete_tx::bytes [%0], [%1], %2, [%3];"
        :: "r"(dst), "l"(src), "r"(bytes), "r"(bar) : "memory");
}

// One 256-thread block per row. Bulk-async (TMA engine) streams the row
// through a 3-slot SMEM ring — outstanding bytes bounded by SMEM, not by
// LSU/L1tex queue entries (the suspected 60%-of-HBM cap in R3-R6).
__global__ void __launch_bounds__(256) cosarc_fused_kernel(
    const float* __restrict__ preds,
    const int* __restrict__ labels,      // int32 (JAX x64 disabled)
    float* __restrict__ out,
    int V, int B)
{
    __shared__ __align__(128) float buf[NSLOTS][TILE_FLOATS];
    __shared__ __align__(8) unsigned long long full_bar[NSLOTS];
    __shared__ float warpsum[8];

    const int tid = threadIdx.x;
    const int wid = tid >> 5;
    const int lid = tid & 31;
    const int row = blockIdx.x;
    const float* rp = preds + (size_t)row * (size_t)V;
    const int ntiles = (V + TILE_FLOATS - 1) / TILE_FLOATS;

    if (tid == 0) {
        #pragma unroll
        for (int s = 0; s < NSLOTS; s++)
            mbar_init(smem_u32(&full_bar[s]), 1);
    }
    __syncthreads();

    // Prologue: put DEPTH tiles in flight.
    if (tid == 0) {
        #pragma unroll
        for (int d = 0; d < DEPTH; d++) {
            if (d < ntiles) {
                int nf = V - d * TILE_FLOATS; if (nf > TILE_FLOATS) nf = TILE_FLOATS;
                unsigned int bar = smem_u32(&full_bar[d]);
                mbar_expect_tx(bar, (unsigned)nf * 4u);
                bulk_g2s(smem_u32(&buf[d][0]), rp + d * TILE_FLOATS, (unsigned)nf * 4u, bar);
            }
        }
    }

    const float C = 30.0f * 1.4426950408889634f;   // exp(30x) = exp2(C*x)
    float s0 = 0.f, s1 = 0.f;

    int slot = 0, parity = 0;
    for (int t = 0; t < ntiles; t++) {
        mbar_wait(smem_u32(&full_bar[slot]), parity);

        int nf4 = V - t * TILE_FLOATS; if (nf4 > TILE_FLOATS) nf4 = TILE_FLOATS;
        nf4 >>= 2;
        const float4* bp = reinterpret_cast<const float4*>(&buf[slot][0]);
        for (int i = tid; i < nf4; i += 256) {
            float4 v = bp[i];
            s0 += ex2(v.x * C) + ex2(v.y * C);
            s1 += ex2(v.z * C) + ex2(v.w * C);
        }
        __syncthreads();   // slot fully consumed -> safe to refill

        int nt = t + DEPTH;
        if (tid == 0 && nt < ntiles) {
            int nslot = nt % NSLOTS;
            int nf = V - nt * TILE_FLOATS; if (nf > TILE_FLOATS) nf = TILE_FLOATS;
            unsigned int bar = smem_u32(&full_bar[nslot]);
            mbar_expect_tx(bar, (unsigned)nf * 4u);
            bulk_g2s(smem_u32(&buf[nslot][0]), rp + nt * TILE_FLOATS, (unsigned)nf * 4u, bar);
        }

        if (++slot == NSLOTS) { slot = 0; parity ^= 1; }
    }
    // Scalar tail (V % 4 != 0) — not hit for V=32000.
    for (int j = (V & ~3) + tid; j < V; j += 256)
        s0 += ex2(rp[j] * C);

    float sum = s0 + s1;
    #pragma unroll
    for (int o = 16; o > 0; o >>= 1)
        sum += __shfl_xor_sync(0xffffffffu, sum, o);
    if (lid == 0) warpsum[wid] = sum;
    __syncthreads();

    if (tid == 0) {
        float tot = 0.f;
        #pragma unroll
        for (int w = 0; w < 8; w++) tot += warpsum[w];

        int lab = labels[row];
        if (lab < 0) lab = 0;
        if (lab >= V) lab = V - 1;
        const float target = rp[lab];

        double sum_others = (double)tot - (double)ex2(target * C);

        const double EPS = 1e-12;
        const double PI  = 3.14159265358979323846;
        double t = (double)target;
        t = fmin(fmax(t, -1.0 + EPS), 1.0 - EPS);
        double theta = acos(t);
        theta = fmin(fmax(theta, EPS), PI - EPS);
        double numerator = 30.0 * (cos(theta + 0.5) - 0.35);
        double denominator = exp(numerator) + sum_others;
        g_row_loss[row] = numerator - log(denominator);
    }

    // ---- last-block-done final reduction (deterministic fixed-order sum) ----
    __threadfence();
    __shared__ bool is_last;
    if (tid == 0)
        is_last = (atomicAdd(&g_done, 1u) == (unsigned)(gridDim.x - 1));
    __syncthreads();

    if (is_last) {
        double d = 0.0;
        for (int j = tid; j < B; j += 256)
            d += g_row_loss[j];
        #pragma unroll
        for (int o = 16; o > 0; o >>= 1)
            d += __shfl_xor_sync(0xffffffffu, d, o);

        __shared__ double dwarp[8];
        if (lid == 0) dwarp[wid] = d;
        __syncthreads();

        if (tid == 0) {
            double tot = 0.0;
            #pragma unroll
            for (int w = 0; w < 8; w++) tot += dwarp[w];
            out[0] = (float)(-tot / (double)B);
            g_done = 0;   // reset for next graph replay
        }
    }
}

extern "C" void kernel_launch(void* const* d_in, const int* in_sizes, int n_in,
                              void* d_out, int out_size)
{
    const float* preds  = (const float*)d_in[0];
    const int*   labels = (const int*)d_in[1];

    const int B = in_sizes[1];                 // 2048
    const int V = in_sizes[0] / B;             // 32000

    cosarc_fused_kernel<<<B, 256>>>(preds, labels, (float*)d_out, V, B);
}

// round 8
// speedup vs baseline: 1.1405x; 1.1405x over previous
#include <cuda_runtime.h>
#include <cuda_bf16.h>

#define MAX_ROWS 8192
#define NTHR 320          // 8000 float4 per row / 320 = exactly 25 per thread
#define NWARP (NTHR / 32)

__device__ double g_row_loss[MAX_ROWS];
__device__ unsigned int g_done = 0;   // self-resets -> graph-replay safe

__device__ __forceinline__ float ex2(float x) {
    float y;
    asm("ex2.approx.f32 %0, %1;" : "=f"(y) : "f"(x));
    return y;
}

// One 320-thread block per row. V==32000 fast path: fully unrolled 25x
// LDG.128 with immediate offsets -> ~13 instructions per 512B warp-chunk
// (R3-R7 post-mortem: designs were issue-bloat-capped at 33-61 instr/chunk,
// which caps BW at ~4.7 TB/s regardless of MLP/occupancy/TMA).
__global__ void __launch_bounds__(NTHR, 6) cosarc_fused_kernel(
    const float* __restrict__ preds,
    const int* __restrict__ labels,     // int32 (JAX x64 disabled)
    float* __restrict__ out,
    int V, int B)
{
    const int tid = threadIdx.x;
    const int wid = tid >> 5;
    const int lid = tid & 31;
    const int row = blockIdx.x;
    const float* rp = preds + (size_t)row * (size_t)V;

    const float C = 30.0f * 1.4426950408889634f;   // exp(30x) = exp2(C*x)
    float s0 = 0.f, s1 = 0.f, s2 = 0.f, s3 = 0.f;

    if (V == 32000) {
        // Fast path: 8000 float4, 25 per thread, stride 320, zero index math.
        const float4* p4 = reinterpret_cast<const float4*>(rp) + tid;
        #pragma unroll
        for (int k = 0; k < 25; k++) {
            float4 v = __ldg(p4 + k * NTHR);
            s0 += ex2(v.x * C);
            s1 += ex2(v.y * C);
            s2 += ex2(v.z * C);
            s3 += ex2(v.w * C);
        }
    } else {
        const float4* p4 = reinterpret_cast<const float4*>(rp);
        const int n4 = V >> 2;
        for (int i = tid; i < n4; i += NTHR) {
            float4 v = __ldg(&p4[i]);
            s0 += ex2(v.x * C);
            s1 += ex2(v.y * C);
            s2 += ex2(v.z * C);
            s3 += ex2(v.w * C);
        }
        for (int j = (n4 << 2) + tid; j < V; j += NTHR)
            s0 += ex2(rp[j] * C);
    }

    float sum = (s0 + s1) + (s2 + s3);

    #pragma unroll
    for (int o = 16; o > 0; o >>= 1)
        sum += __shfl_xor_sync(0xffffffffu, sum, o);

    __shared__ float warpsum[NWARP];
    if (lid == 0) warpsum[wid] = sum;
    __syncthreads();

    if (tid == 0) {
        float tot = 0.f;
        #pragma unroll
        for (int w = 0; w < NWARP; w++) tot += warpsum[w];

        int lab = labels[row];
        if (lab < 0) lab = 0;
        if (lab >= V) lab = V - 1;
        const float target = rp[lab];

        double sum_others = (double)tot - (double)ex2(target * C);

        const double EPS = 1e-12;
        const double PI  = 3.14159265358979323846;
        double t = (double)target;
        t = fmin(fmax(t, -1.0 + EPS), 1.0 - EPS);
        double theta = acos(t);
        theta = fmin(fmax(theta, EPS), PI - EPS);
        double numerator = 30.0 * (cos(theta + 0.5) - 0.35);
        double denominator = exp(numerator) + sum_others;
        g_row_loss[row] = numerator - log(denominator);
    }

    // ---- last-block-done final reduction (deterministic fixed-order sum) ----
    __threadfence();
    __shared__ bool is_last;
    if (tid == 0)
        is_last = (atomicAdd(&g_done, 1u) == (unsigned)(gridDim.x - 1));
    __syncthreads();

    if (is_last) {
        double d = 0.0;
        for (int j = tid; j < B; j += NTHR)
            d += g_row_loss[j];

        #pragma unroll
        for (int o = 16; o > 0; o >>= 1)
            d += __shfl_xor_sync(0xffffffffu, d, o);

        __shared__ double dwarp[NWARP];
        if (lid == 0) dwarp[wid] = d;
        __syncthreads();

        if (tid == 0) {
            double tot = 0.0;
            #pragma unroll
            for (int w = 0; w < NWARP; w++) tot += dwarp[w];
            out[0] = (float)(-tot / (double)B);
            g_done = 0;   // reset for next graph replay
        }
    }
}

extern "C" void kernel_launch(void* const* d_in, const int* in_sizes, int n_in,
                              void* d_out, int out_size)
{
    const float* preds  = (const float*)d_in[0];
    const int*   labels = (const int*)d_in[1];

    const int B = in_sizes[1];                 // 2048
    const int V = in_sizes[0] / B;             // 32000

    cosarc_fused_kernel<<<B, NTHR>>>(preds, labels, (float*)d_out, V, B);
}